// round 3
// baseline (speedup 1.0000x reference)
#include <cuda_runtime.h>
#include <cuda_bf16.h>
#include <math.h>
#include <stdint.h>

// Problem constants
#define T_LEN 2048
#define B_DIM 2
#define E_DIM 1024
#define H_NUM 16
#define HD 64
#define M_ROWS (T_LEN * B_DIM)       // 4096
#define E3 (3 * E_DIM)               // 3072
#define NHEADS (B_DIM * H_NUM)       // 32
#define OUT_ELEMS ((size_t)T_LEN * B_DIM * E_DIM)

#define STAGES 4

// Scratch in device globals (no allocation allowed)
__device__ float g_qkv[(size_t)M_ROWS * E3];        // 48 MB
__device__ float g_vt[(size_t)NHEADS * HD * T_LEN]; // 16 MB
__device__ float g_attn[(size_t)M_ROWS * E_DIM];    // 16 MB

__device__ __forceinline__ uint32_t f2tf(float f) {
    uint32_t u;
    asm("cvt.rna.tf32.f32 %0, %1;" : "=r"(u) : "f"(f));
    return u;
}

__device__ __forceinline__ void mma_tf32(float c[4], const uint32_t a[4], const uint32_t b[2]) {
    asm volatile(
        "mma.sync.aligned.m16n8k8.row.col.f32.tf32.tf32.f32 "
        "{%0,%1,%2,%3}, {%4,%5,%6,%7}, {%8,%9}, {%0,%1,%2,%3};\n"
        : "+f"(c[0]), "+f"(c[1]), "+f"(c[2]), "+f"(c[3])
        : "r"(a[0]), "r"(a[1]), "r"(a[2]), "r"(a[3]), "r"(b[0]), "r"(b[1]));
}

__device__ __forceinline__ void cp_async16(float* smem_dst, const float* gmem_src) {
    uint32_t dst = (uint32_t)__cvta_generic_to_shared(smem_dst);
    asm volatile("cp.async.ca.shared.global [%0], [%1], 16;\n" :: "r"(dst), "l"(gmem_src));
}
__device__ __forceinline__ void cp_commit() {
    asm volatile("cp.async.commit_group;\n");
}
template <int N>
__device__ __forceinline__ void cp_wait() {
    asm volatile("cp.async.wait_group %0;\n" :: "n"(N));
}

// ---------------------------------------------------------------------------
// Tensor-core NT GEMM, 4-stage cp.async pipeline:
//   C[M,N] = scale * A[M,K] @ B[N,K]^T + bias[N]
// 256 threads, BK=16, mma.m16n8k8.tf32, dynamic smem.
// Requires M%BM==0, N%BN==0, K%16==0, K>=64, rows 16B-aligned.
// ---------------------------------------------------------------------------
template <int BM, int BN, int WARPS_M, int WARPS_N>
__device__ __forceinline__ void gemm_tc_pipe(
    const float* __restrict__ A, int lda,
    const float* __restrict__ B, int ldb,
    float* __restrict__ C, int ldc,
    int K, float scale, const float* __restrict__ bias)
{
    constexpr int BK = 16;
    constexpr int LD = 20;                    // conflict-free padding
    constexpr int WTM = BM / WARPS_M;
    constexpr int WTN = BN / WARPS_N;
    constexpr int MT = WTM / 16;
    constexpr int NT = WTN / 8;
    constexpr int AR = (BM * 4) / 256;        // float4 copies/thread for A tile
    constexpr int BR = (BN * 4) / 256;

    extern __shared__ float smem[];
    float* Asm = smem;                        // STAGES * BM * LD
    float* Bsm = smem + STAGES * BM * LD;     // STAGES * BN * LD

    const int tid  = threadIdx.x;
    const int lane = tid & 31;
    const int warp = tid >> 5;
    const int wm = warp % WARPS_M;
    const int wn = warp / WARPS_M;
    const int g   = lane >> 2;
    const int tig = lane & 3;

    const int blockM = blockIdx.y * BM;
    const int blockN = blockIdx.x * BN;
    const float* Ab = A + (size_t)blockM * lda;
    const float* Bb = B + (size_t)blockN * ldb;

    float acc[MT][NT][4];
#pragma unroll
    for (int mi = 0; mi < MT; mi++)
#pragma unroll
        for (int ni = 0; ni < NT; ni++)
#pragma unroll
            for (int j = 0; j < 4; j++) acc[mi][ni][j] = 0.0f;

    auto issue_copy = [&](int stage, int k0) {
        float* as = Asm + stage * BM * LD;
        float* bs = Bsm + stage * BN * LD;
#pragma unroll
        for (int j = 0; j < AR; j++) {
            int i = tid + j * 256;
            int row = i >> 2, c = (i & 3) * 4;
            cp_async16(&as[row * LD + c], Ab + (size_t)row * lda + k0 + c);
        }
#pragma unroll
        for (int j = 0; j < BR; j++) {
            int i = tid + j * 256;
            int row = i >> 2, c = (i & 3) * 4;
            cp_async16(&bs[row * LD + c], Bb + (size_t)row * ldb + k0 + c);
        }
    };

    auto compute = [&](int stage) {
        const float* as = Asm + stage * BM * LD;
        const float* bs = Bsm + stage * BN * LD;
#pragma unroll
        for (int ks = 0; ks < BK; ks += 8) {
            uint32_t af[MT][4];
            uint32_t bf[NT][2];
#pragma unroll
            for (int mi = 0; mi < MT; mi++) {
                int m = wm * WTM + mi * 16;
                af[mi][0] = f2tf(as[(m + g) * LD + ks + tig]);
                af[mi][1] = f2tf(as[(m + g + 8) * LD + ks + tig]);
                af[mi][2] = f2tf(as[(m + g) * LD + ks + tig + 4]);
                af[mi][3] = f2tf(as[(m + g + 8) * LD + ks + tig + 4]);
            }
#pragma unroll
            for (int ni = 0; ni < NT; ni++) {
                int n = wn * WTN + ni * 8;
                bf[ni][0] = f2tf(bs[(n + g) * LD + ks + tig]);
                bf[ni][1] = f2tf(bs[(n + g) * LD + ks + tig + 4]);
            }
#pragma unroll
            for (int mi = 0; mi < MT; mi++)
#pragma unroll
                for (int ni = 0; ni < NT; ni++)
                    mma_tf32(acc[mi][ni], af[mi], bf[ni]);
        }
    };

    const int nk = K / BK;

    // Prologue: fill STAGES-1 stages
#pragma unroll
    for (int s = 0; s < STAGES - 1; s++) {
        issue_copy(s, s * BK);
        cp_commit();
    }

    for (int it = 0; it < nk; it++) {
        cp_wait<STAGES - 2>();
        __syncthreads();
        compute(it % STAGES);
        __syncthreads();
        int nxt = it + STAGES - 1;
        if (nxt < nk) issue_copy(nxt % STAGES, nxt * BK);
        cp_commit();
    }

    // Epilogue
#pragma unroll
    for (int mi = 0; mi < MT; mi++) {
#pragma unroll
        for (int ni = 0; ni < NT; ni++) {
            int m0 = blockM + wm * WTM + mi * 16 + g;
            int n0 = blockN + wn * WTN + ni * 8 + 2 * tig;
            float b0 = bias ? bias[n0] : 0.0f;
            float b1 = bias ? bias[n0 + 1] : 0.0f;
            float2 v0 = {acc[mi][ni][0] * scale + b0, acc[mi][ni][1] * scale + b1};
            float2 v1 = {acc[mi][ni][2] * scale + b0, acc[mi][ni][3] * scale + b1};
            *(float2*)(C + (size_t)m0 * ldc + n0) = v0;
            *(float2*)(C + (size_t)(m0 + 8) * ldc + n0) = v1;
        }
    }
}

// ---------------------------------------------------------------------------
// Kernel wrappers
// ---------------------------------------------------------------------------

__global__ void __launch_bounds__(256) k_qkv(const float* __restrict__ g,
                                             const float* __restrict__ Win,
                                             const float* __restrict__ bin)
{
    gemm_tc_pipe<128, 128, 2, 4>(g, E_DIM, Win, E_DIM, g_qkv, E3, E_DIM, 1.0f, bin);
}

__global__ void k_build_vt()
{
    size_t idx = (size_t)blockIdx.x * blockDim.x + threadIdx.x;
    int s = (int)(idx % T_LEN);
    int rest = (int)(idx / T_LEN);
    int d = rest % HD;
    int bh = rest / HD;
    int b = bh >> 4;
    int h = bh & 15;
    g_vt[idx] = g_qkv[(size_t)(s * B_DIM + b) * E3 + 2 * E_DIM + h * HD + d];
}

__global__ void __launch_bounds__(256) k_scores(float* __restrict__ P)
{
    int bh = blockIdx.z;
    int b = bh >> 4;
    int h = bh & 15;
    const float* A  = g_qkv + (size_t)b * E3 + h * HD;
    const float* Bm = g_qkv + (size_t)b * E3 + E_DIM + h * HD;
    float* C = P + (size_t)bh * T_LEN * T_LEN;
    gemm_tc_pipe<128, 128, 2, 4>(A, B_DIM * E3, Bm, B_DIM * E3, C, T_LEN, HD, 0.125f, nullptr);
}

__global__ void k_softmax(float* __restrict__ P)
{
    float* row = P + (size_t)blockIdx.x * T_LEN;
    const int tid = threadIdx.x;   // 256 threads
    float vals[8];
    float m = -INFINITY;
#pragma unroll
    for (int i = 0; i < 8; i++) {
        vals[i] = row[tid + i * 256];
        m = fmaxf(m, vals[i]);
    }
    __shared__ float red[32];
#pragma unroll
    for (int o = 16; o > 0; o >>= 1)
        m = fmaxf(m, __shfl_xor_sync(0xFFFFFFFFu, m, o));
    if ((tid & 31) == 0) red[tid >> 5] = m;
    __syncthreads();
    if (tid < 32) {
        float v = (tid < 8) ? red[tid] : -INFINITY;
#pragma unroll
        for (int o = 4; o > 0; o >>= 1)
            v = fmaxf(v, __shfl_xor_sync(0xFFFFFFFFu, v, o));
        if (tid == 0) red[0] = v;
    }
    __syncthreads();
    m = red[0];

    float sum = 0.0f;
#pragma unroll
    for (int i = 0; i < 8; i++) {
        vals[i] = expf(vals[i] - m);
        sum += vals[i];
    }
    __syncthreads();
#pragma unroll
    for (int o = 16; o > 0; o >>= 1)
        sum += __shfl_xor_sync(0xFFFFFFFFu, sum, o);
    if ((tid & 31) == 0) red[tid >> 5] = sum;
    __syncthreads();
    if (tid < 32) {
        float v = (tid < 8) ? red[tid] : 0.0f;
#pragma unroll
        for (int o = 4; o > 0; o >>= 1)
            v += __shfl_xor_sync(0xFFFFFFFFu, v, o);
        if (tid == 0) red[0] = v;
    }
    __syncthreads();
    float inv = 1.0f / red[0];
#pragma unroll
    for (int i = 0; i < 8; i++)
        row[tid + i * 256] = vals[i] * inv;
}

__global__ void __launch_bounds__(256) k_pv(const float* __restrict__ P)
{
    int bh = blockIdx.z;
    int b = bh >> 4;
    int h = bh & 15;
    const float* A  = P + (size_t)bh * T_LEN * T_LEN;
    const float* Bm = g_vt + (size_t)bh * HD * T_LEN;
    float* C = g_attn + (size_t)b * E_DIM + h * HD;
    gemm_tc_pipe<128, 64, 4, 2>(A, T_LEN, Bm, T_LEN, C, B_DIM * E_DIM, T_LEN, 1.0f, nullptr);
}

__global__ void __launch_bounds__(256) k_out(const float* __restrict__ Wout,
                                             const float* __restrict__ bout,
                                             float* __restrict__ out)
{
    gemm_tc_pipe<128, 128, 2, 4>(g_attn, E_DIM, Wout, E_DIM, out, E_DIM, E_DIM, 1.0f, bout);
}

// ---------------------------------------------------------------------------
extern "C" void kernel_launch(void* const* d_in, const int* in_sizes, int n_in,
                              void* d_out, int out_size)
{
    const float* g    = (const float*)d_in[0];
    const float* Win  = (const float*)d_in[1];
    const float* bin  = (const float*)d_in[2];
    const float* Wout = (const float*)d_in[3];
    const float* bout = (const float*)d_in[4];

    float* out = (float*)d_out;
    float* P   = (float*)d_out + OUT_ELEMS;

    constexpr int SMEM_128 = STAGES * (128 + 128) * 20 * 4;   // 81920
    constexpr int SMEM_PV  = STAGES * (128 + 64) * 20 * 4;    // 61440

    static bool attr_set = false;
    if (!attr_set) {
        cudaFuncSetAttribute(k_qkv,    cudaFuncAttributeMaxDynamicSharedMemorySize, SMEM_128);
        cudaFuncSetAttribute(k_scores, cudaFuncAttributeMaxDynamicSharedMemorySize, SMEM_128);
        cudaFuncSetAttribute(k_out,    cudaFuncAttributeMaxDynamicSharedMemorySize, SMEM_128);
        cudaFuncSetAttribute(k_pv,     cudaFuncAttributeMaxDynamicSharedMemorySize, SMEM_PV);
        attr_set = true;
    }

    // 1. QKV projection
    k_qkv<<<dim3(E3 / 128, M_ROWS / 128), 256, SMEM_128>>>(g, Win, bin);

    // 2. V transpose
    k_build_vt<<<(int)((size_t)NHEADS * HD * T_LEN / 256), 256>>>();

    // 3. Scores into P region
    k_scores<<<dim3(T_LEN / 128, T_LEN / 128, NHEADS), 256, SMEM_128>>>(P);

    // 4. Row softmax in place
    k_softmax<<<NHEADS * T_LEN, 256>>>(P);

    // 5. attn = P @ V
    k_pv<<<dim3(1, T_LEN / 128, NHEADS), 256, SMEM_PV>>>(P);

    // 6. Output projection
    k_out<<<dim3(E_DIM / 128, M_ROWS / 128), 256, SMEM_128>>>(Wout, bout, out);
}

// round 5
// speedup vs baseline: 1.6586x; 1.6586x over previous
#include <cuda_runtime.h>
#include <cuda_fp16.h>
#include <math.h>
#include <stdint.h>

// Problem constants
#define T_LEN 2048
#define B_DIM 2
#define E_DIM 1024
#define H_NUM 16
#define HD 64
#define M_ROWS (T_LEN * B_DIM)       // 4096
#define E3 (3 * E_DIM)               // 3072
#define NHEADS (B_DIM * H_NUM)       // 32
#define OUT_ELEMS ((size_t)T_LEN * B_DIM * E_DIM)

// Scratch in device globals (all fp32 — conversion to fp16 only inside GEMM smem)
__device__ float g_qkv[(size_t)M_ROWS * E3];        // 48 MB
__device__ float g_vt[(size_t)NHEADS * HD * T_LEN]; // 16 MB
__device__ float g_attn[(size_t)M_ROWS * E_DIM];    // 16 MB

__device__ __forceinline__ uint32_t pack_h2(float lo, float hi) {
    uint32_t r;
    asm("cvt.rn.f16x2.f32 %0, %1, %2;" : "=r"(r) : "f"(hi), "f"(lo));
    return r;
}

__device__ __forceinline__ void mma_f16(float c[4], const uint32_t a[4], const uint32_t b[2]) {
    asm volatile(
        "mma.sync.aligned.m16n8k16.row.col.f32.f16.f16.f32 "
        "{%0,%1,%2,%3}, {%4,%5,%6,%7}, {%8,%9}, {%0,%1,%2,%3};\n"
        : "+f"(c[0]), "+f"(c[1]), "+f"(c[2]), "+f"(c[3])
        : "r"(a[0]), "r"(a[1]), "r"(a[2]), "r"(a[3]), "r"(b[0]), "r"(b[1]));
}

// ---------------------------------------------------------------------------
// fp16 tensor-core NT GEMM: C[M,N] = scale * A[M,K] @ B[N,K]^T + bias[N]
// A,B,C fp32 in gmem; fp16 in smem. BM=128, BK=32 halves, double-buffered,
// 256 threads, mma.m16n8k16. Row pitch LDW=20 words (16 payload + 4 pad)
// gives conflict-free fragment LDS (stride-20 pattern).
// Requires M%128==0, N%BN==0, K%32==0, rows 16B-aligned.
// ---------------------------------------------------------------------------
template <int BN, int WARPS_M, int WARPS_N>
__device__ __forceinline__ void gemm_fp16(
    const float* __restrict__ A, int lda,
    const float* __restrict__ B, int ldb,
    float* __restrict__ C, int ldc,
    int K, float scale, const float* __restrict__ bias)
{
    constexpr int BM = 128;
    constexpr int BK = 32;                 // k elems (halves) per chunk
    constexpr int LDW = 20;                // 32-bit words per row in smem
    constexpr int WTM = BM / WARPS_M;
    constexpr int WTN = BN / WARPS_N;
    constexpr int MT = WTM / 16;
    constexpr int NT = WTN / 8;
    constexpr int AU = BM * 4 / 256;       // 16B-units per thread for A tile
    constexpr int BU = BN * 4 / 256;

    __shared__ uint32_t As[2][BM * LDW];
    __shared__ uint32_t Bs[2][BN * LDW];

    const int tid  = threadIdx.x;
    const int lane = tid & 31;
    const int warp = tid >> 5;
    const int wm = warp % WARPS_M;
    const int wn = warp / WARPS_M;
    const int g   = lane >> 2;
    const int tig = lane & 3;

    const int blockM = blockIdx.y * BM;
    const int blockN = blockIdx.x * BN;
    const float* Ab = A + (size_t)blockM * lda;
    const float* Bb = B + (size_t)blockN * ldb;

    float acc[MT][NT][4];
#pragma unroll
    for (int mi = 0; mi < MT; mi++)
#pragma unroll
        for (int ni = 0; ni < NT; ni++)
#pragma unroll
            for (int j = 0; j < 4; j++) acc[mi][ni][j] = 0.0f;

    float4 ra[2 * AU], rb[2 * BU];

    auto load_tiles = [&](int k0) {
#pragma unroll
        for (int j = 0; j < AU; j++) {
            int u = tid + j * 256;
            int row = u >> 2, c = u & 3;               // c: 16B unit = 8 halves
            const float* p = Ab + (size_t)row * lda + k0 + c * 8;
            ra[2 * j]     = *(const float4*)(p);
            ra[2 * j + 1] = *(const float4*)(p + 4);
        }
#pragma unroll
        for (int j = 0; j < BU; j++) {
            int u = tid + j * 256;
            int row = u >> 2, c = u & 3;
            const float* p = Bb + (size_t)row * ldb + k0 + c * 8;
            rb[2 * j]     = *(const float4*)(p);
            rb[2 * j + 1] = *(const float4*)(p + 4);
        }
    };
    auto store_tiles = [&](int buf) {
#pragma unroll
        for (int j = 0; j < AU; j++) {
            int u = tid + j * 256;
            int row = u >> 2, c = u & 3;
            float4 f0 = ra[2 * j], f1 = ra[2 * j + 1];
            uint4 v = {pack_h2(f0.x, f0.y), pack_h2(f0.z, f0.w),
                       pack_h2(f1.x, f1.y), pack_h2(f1.z, f1.w)};
            *(uint4*)&As[buf][row * LDW + c * 4] = v;
        }
#pragma unroll
        for (int j = 0; j < BU; j++) {
            int u = tid + j * 256;
            int row = u >> 2, c = u & 3;
            float4 f0 = rb[2 * j], f1 = rb[2 * j + 1];
            uint4 v = {pack_h2(f0.x, f0.y), pack_h2(f0.z, f0.w),
                       pack_h2(f1.x, f1.y), pack_h2(f1.z, f1.w)};
            *(uint4*)&Bs[buf][row * LDW + c * 4] = v;
        }
    };
    auto compute = [&](int buf) {
#pragma unroll
        for (int ks2 = 0; ks2 < 2; ks2++) {            // two k16 steps per BK=32
            const int base = ks2 * 8;
            uint32_t af[MT][4];
            uint32_t bf[NT][2];
#pragma unroll
            for (int mi = 0; mi < MT; mi++) {
                int m = wm * WTM + mi * 16;
                const uint32_t* a = As[buf];
                af[mi][0] = a[(m + g) * LDW + base + tig];
                af[mi][1] = a[(m + g + 8) * LDW + base + tig];
                af[mi][2] = a[(m + g) * LDW + base + tig + 4];
                af[mi][3] = a[(m + g + 8) * LDW + base + tig + 4];
            }
#pragma unroll
            for (int ni = 0; ni < NT; ni++) {
                int n = wn * WTN + ni * 8;
                const uint32_t* b = Bs[buf];
                bf[ni][0] = b[(n + g) * LDW + base + tig];
                bf[ni][1] = b[(n + g) * LDW + base + tig + 4];
            }
#pragma unroll
            for (int mi = 0; mi < MT; mi++)
#pragma unroll
                for (int ni = 0; ni < NT; ni++)
                    mma_f16(acc[mi][ni], af[mi], bf[ni]);
        }
    };

    const int nk = K / BK;
    load_tiles(0);
    store_tiles(0);
    __syncthreads();

    for (int it = 0; it < nk; it++) {
        int cur = it & 1;
        if (it + 1 < nk) load_tiles((it + 1) * BK);
        compute(cur);
        if (it + 1 < nk) {
            store_tiles(cur ^ 1);
            __syncthreads();
        }
    }

    // Epilogue
#pragma unroll
    for (int mi = 0; mi < MT; mi++) {
#pragma unroll
        for (int ni = 0; ni < NT; ni++) {
            int m0 = blockM + wm * WTM + mi * 16 + g;
            int n0 = blockN + wn * WTN + ni * 8 + 2 * tig;
            float b0 = bias ? bias[n0] : 0.0f;
            float b1 = bias ? bias[n0 + 1] : 0.0f;
            float2 v0 = {acc[mi][ni][0] * scale + b0, acc[mi][ni][1] * scale + b1};
            float2 v1 = {acc[mi][ni][2] * scale + b0, acc[mi][ni][3] * scale + b1};
            *(float2*)(C + (size_t)m0 * ldc + n0) = v0;
            *(float2*)(C + (size_t)(m0 + 8) * ldc + n0) = v1;
        }
    }
}

// ---------------------------------------------------------------------------
// Kernel wrappers
// ---------------------------------------------------------------------------

__global__ void __launch_bounds__(256) k_qkv(const float* __restrict__ g,
                                             const float* __restrict__ Win,
                                             const float* __restrict__ bin)
{
    gemm_fp16<128, 2, 4>(g, E_DIM, Win, E_DIM, g_qkv, E3, E_DIM, 1.0f, bin);
}

__global__ void k_build_vt()
{
    size_t idx = (size_t)blockIdx.x * blockDim.x + threadIdx.x;
    int s = (int)(idx % T_LEN);
    int rest = (int)(idx / T_LEN);
    int d = rest % HD;
    int bh = rest / HD;
    int b = bh >> 4;
    int h = bh & 15;
    g_vt[idx] = g_qkv[(size_t)(s * B_DIM + b) * E3 + 2 * E_DIM + h * HD + d];
}

__global__ void __launch_bounds__(256) k_scores(float* __restrict__ P)
{
    int bh = blockIdx.z;
    int b = bh >> 4;
    int h = bh & 15;
    const float* A  = g_qkv + (size_t)b * E3 + h * HD;
    const float* Bm = g_qkv + (size_t)b * E3 + E_DIM + h * HD;
    float* C = P + (size_t)bh * T_LEN * T_LEN;
    gemm_fp16<128, 2, 4>(A, B_DIM * E3, Bm, B_DIM * E3, C, T_LEN, HD, 0.125f, nullptr);
}

__global__ void k_softmax(float* __restrict__ P)
{
    float* row = P + (size_t)blockIdx.x * T_LEN;
    const int tid = threadIdx.x;   // 256 threads
    float vals[8];
    float m = -INFINITY;
#pragma unroll
    for (int i = 0; i < 8; i++) {
        vals[i] = row[tid + i * 256];
        m = fmaxf(m, vals[i]);
    }
    __shared__ float red[32];
#pragma unroll
    for (int o = 16; o > 0; o >>= 1)
        m = fmaxf(m, __shfl_xor_sync(0xFFFFFFFFu, m, o));
    if ((tid & 31) == 0) red[tid >> 5] = m;
    __syncthreads();
    if (tid < 32) {
        float v = (tid < 8) ? red[tid] : -INFINITY;
#pragma unroll
        for (int o = 4; o > 0; o >>= 1)
            v = fmaxf(v, __shfl_xor_sync(0xFFFFFFFFu, v, o));
        if (tid == 0) red[0] = v;
    }
    __syncthreads();
    m = red[0];

    float sum = 0.0f;
#pragma unroll
    for (int i = 0; i < 8; i++) {
        vals[i] = expf(vals[i] - m);
        sum += vals[i];
    }
    __syncthreads();
#pragma unroll
    for (int o = 16; o > 0; o >>= 1)
        sum += __shfl_xor_sync(0xFFFFFFFFu, sum, o);
    if ((tid & 31) == 0) red[tid >> 5] = sum;
    __syncthreads();
    if (tid < 32) {
        float v = (tid < 8) ? red[tid] : 0.0f;
#pragma unroll
        for (int o = 4; o > 0; o >>= 1)
            v += __shfl_xor_sync(0xFFFFFFFFu, v, o);
        if (tid == 0) red[0] = v;
    }
    __syncthreads();
    float inv = 1.0f / red[0];
#pragma unroll
    for (int i = 0; i < 8; i++)
        row[tid + i * 256] = vals[i] * inv;
}

__global__ void __launch_bounds__(256) k_pv(const float* __restrict__ P)
{
    int bh = blockIdx.z;
    int b = bh >> 4;
    int h = bh & 15;
    const float* A  = P + (size_t)bh * T_LEN * T_LEN;
    const float* Bm = g_vt + (size_t)bh * HD * T_LEN;
    float* C = g_attn + (size_t)b * E_DIM + h * HD;
    gemm_fp16<64, 4, 2>(A, T_LEN, Bm, T_LEN, C, B_DIM * E_DIM, T_LEN, 1.0f, nullptr);
}

__global__ void __launch_bounds__(256) k_out(const float* __restrict__ Wout,
                                             const float* __restrict__ bout,
                                             float* __restrict__ out)
{
    gemm_fp16<128, 2, 4>(g_attn, E_DIM, Wout, E_DIM, out, E_DIM, E_DIM, 1.0f, bout);
}

// ---------------------------------------------------------------------------
extern "C" void kernel_launch(void* const* d_in, const int* in_sizes, int n_in,
                              void* d_out, int out_size)
{
    const float* g    = (const float*)d_in[0];
    const float* Win  = (const float*)d_in[1];
    const float* bin  = (const float*)d_in[2];
    const float* Wout = (const float*)d_in[3];
    const float* bout = (const float*)d_in[4];

    float* out = (float*)d_out;
    float* P   = (float*)d_out + OUT_ELEMS;

    // 1. QKV projection: [4096,3072] = [4096,1024] @ [3072,1024]^T + b_in
    k_qkv<<<dim3(E3 / 128, M_ROWS / 128), 256>>>(g, Win, bin);

    // 2. V transpose
    k_build_vt<<<(int)((size_t)NHEADS * HD * T_LEN / 256), 256>>>();

    // 3. Scores into P region of d_out
    k_scores<<<dim3(T_LEN / 128, T_LEN / 128, NHEADS), 256>>>(P);

    // 4. Row softmax in place
    k_softmax<<<NHEADS * T_LEN, 256>>>(P);

    // 5. attn = P @ V
    k_pv<<<dim3(1, T_LEN / 128, NHEADS), 256>>>(P);

    // 6. Output projection
    k_out<<<dim3(E_DIM / 128, M_ROWS / 128), 256>>>(Wout, bout, out);
}

// round 6
// speedup vs baseline: 1.7493x; 1.0547x over previous
#include <cuda_runtime.h>
#include <cuda_fp16.h>
#include <math.h>
#include <stdint.h>

// Problem constants
#define T_LEN 2048
#define B_DIM 2
#define E_DIM 1024
#define H_NUM 16
#define HD 64
#define M_ROWS (T_LEN * B_DIM)       // 4096
#define E3 (3 * E_DIM)               // 3072
#define NHEADS (B_DIM * H_NUM)       // 32
#define NTILE (T_LEN / 128)          // 16 col tiles per row
#define OUT_ELEMS ((size_t)T_LEN * B_DIM * E_DIM)

// Scratch in device globals (all fp32)
__device__ float g_qkv[(size_t)M_ROWS * E3];        // 48 MB
__device__ float g_vt[(size_t)NHEADS * HD * T_LEN]; // 16 MB
__device__ float g_attn[(size_t)M_ROWS * E_DIM];    // 16 MB
__device__ float g_pm[(size_t)NHEADS * NTILE * T_LEN];  // partial row max, 4 MB
__device__ float g_pl[(size_t)NHEADS * NTILE * T_LEN];  // partial row sumexp
__device__ float g_m[(size_t)NHEADS * T_LEN];           // final row max
__device__ float g_linv[(size_t)NHEADS * T_LEN];        // final 1/sumexp

__device__ __forceinline__ uint32_t pack_h2(float lo, float hi) {
    uint32_t r;
    asm("cvt.rn.f16x2.f32 %0, %1, %2;" : "=r"(r) : "f"(hi), "f"(lo));
    return r;
}

__device__ __forceinline__ void mma_f16(float c[4], const uint32_t a[4], const uint32_t b[2]) {
    asm volatile(
        "mma.sync.aligned.m16n8k16.row.col.f32.f16.f16.f32 "
        "{%0,%1,%2,%3}, {%4,%5,%6,%7}, {%8,%9}, {%0,%1,%2,%3};\n"
        : "+f"(c[0]), "+f"(c[1]), "+f"(c[2]), "+f"(c[3])
        : "r"(a[0]), "r"(a[1]), "r"(a[2]), "r"(a[3]), "r"(b[0]), "r"(b[1]));
}

// ---------------------------------------------------------------------------
// fp16 tensor-core NT GEMM: C[M,N] = scale * A[M,K] @ B[N,K]^T + bias[N]
// Optional STATS epilogue (for scores): per-block-row softmax partials.
// ---------------------------------------------------------------------------
template <int BN, int WARPS_M, int WARPS_N, bool STATS>
__device__ __forceinline__ void gemm_fp16(
    const float* __restrict__ A, int lda,
    const float* __restrict__ B, int ldb,
    float* __restrict__ C, int ldc,
    int K, float scale, const float* __restrict__ bias,
    float* __restrict__ pm, float* __restrict__ pl)   // per-head stats bases
{
    constexpr int BM = 128;
    constexpr int BK = 32;
    constexpr int LDW = 20;
    constexpr int WTM = BM / WARPS_M;
    constexpr int WTN = BN / WARPS_N;
    constexpr int MT = WTM / 16;
    constexpr int NT = WTN / 8;
    constexpr int AU = BM * 4 / 256;
    constexpr int BU = BN * 4 / 256;

    __shared__ uint32_t As[2][BM * LDW];
    __shared__ uint32_t Bs[2][BN * LDW];

    const int tid  = threadIdx.x;
    const int lane = tid & 31;
    const int warp = tid >> 5;
    const int wm = warp % WARPS_M;
    const int wn = warp / WARPS_M;
    const int g   = lane >> 2;
    const int tig = lane & 3;

    const int blockM = blockIdx.y * BM;
    const int blockN = blockIdx.x * BN;
    const float* Ab = A + (size_t)blockM * lda;
    const float* Bb = B + (size_t)blockN * ldb;

    float acc[MT][NT][4];
#pragma unroll
    for (int mi = 0; mi < MT; mi++)
#pragma unroll
        for (int ni = 0; ni < NT; ni++)
#pragma unroll
            for (int j = 0; j < 4; j++) acc[mi][ni][j] = 0.0f;

    float4 ra[2 * AU], rb[2 * BU];

    auto load_tiles = [&](int k0) {
#pragma unroll
        for (int j = 0; j < AU; j++) {
            int u = tid + j * 256;
            int row = u >> 2, c = u & 3;
            const float* p = Ab + (size_t)row * lda + k0 + c * 8;
            ra[2 * j]     = *(const float4*)(p);
            ra[2 * j + 1] = *(const float4*)(p + 4);
        }
#pragma unroll
        for (int j = 0; j < BU; j++) {
            int u = tid + j * 256;
            int row = u >> 2, c = u & 3;
            const float* p = Bb + (size_t)row * ldb + k0 + c * 8;
            rb[2 * j]     = *(const float4*)(p);
            rb[2 * j + 1] = *(const float4*)(p + 4);
        }
    };
    auto store_tiles = [&](int buf) {
#pragma unroll
        for (int j = 0; j < AU; j++) {
            int u = tid + j * 256;
            int row = u >> 2, c = u & 3;
            float4 f0 = ra[2 * j], f1 = ra[2 * j + 1];
            uint4 v = {pack_h2(f0.x, f0.y), pack_h2(f0.z, f0.w),
                       pack_h2(f1.x, f1.y), pack_h2(f1.z, f1.w)};
            *(uint4*)&As[buf][row * LDW + c * 4] = v;
        }
#pragma unroll
        for (int j = 0; j < BU; j++) {
            int u = tid + j * 256;
            int row = u >> 2, c = u & 3;
            float4 f0 = rb[2 * j], f1 = rb[2 * j + 1];
            uint4 v = {pack_h2(f0.x, f0.y), pack_h2(f0.z, f0.w),
                       pack_h2(f1.x, f1.y), pack_h2(f1.z, f1.w)};
            *(uint4*)&Bs[buf][row * LDW + c * 4] = v;
        }
    };
    auto compute = [&](int buf) {
#pragma unroll
        for (int ks2 = 0; ks2 < 2; ks2++) {
            const int base = ks2 * 8;
            uint32_t af[MT][4];
            uint32_t bf[NT][2];
#pragma unroll
            for (int mi = 0; mi < MT; mi++) {
                int m = wm * WTM + mi * 16;
                const uint32_t* a = As[buf];
                af[mi][0] = a[(m + g) * LDW + base + tig];
                af[mi][1] = a[(m + g + 8) * LDW + base + tig];
                af[mi][2] = a[(m + g) * LDW + base + tig + 4];
                af[mi][3] = a[(m + g + 8) * LDW + base + tig + 4];
            }
#pragma unroll
            for (int ni = 0; ni < NT; ni++) {
                int n = wn * WTN + ni * 8;
                const uint32_t* b = Bs[buf];
                bf[ni][0] = b[(n + g) * LDW + base + tig];
                bf[ni][1] = b[(n + g) * LDW + base + tig + 4];
            }
#pragma unroll
            for (int mi = 0; mi < MT; mi++)
#pragma unroll
                for (int ni = 0; ni < NT; ni++)
                    mma_f16(acc[mi][ni], af[mi], bf[ni]);
        }
    };

    const int nk = K / BK;
    load_tiles(0);
    store_tiles(0);
    __syncthreads();

    for (int it = 0; it < nk; it++) {
        int cur = it & 1;
        if (it + 1 < nk) load_tiles((it + 1) * BK);
        compute(cur);
        if (it + 1 < nk) {
            store_tiles(cur ^ 1);
            __syncthreads();
        }
    }

    // Write C
#pragma unroll
    for (int mi = 0; mi < MT; mi++) {
#pragma unroll
        for (int ni = 0; ni < NT; ni++) {
            int m0 = blockM + wm * WTM + mi * 16 + g;
            int n0 = blockN + wn * WTN + ni * 8 + 2 * tig;
            float b0 = bias ? bias[n0] : 0.0f;
            float b1 = bias ? bias[n0 + 1] : 0.0f;
            float2 v0 = {acc[mi][ni][0] * scale + b0, acc[mi][ni][1] * scale + b1};
            float2 v1 = {acc[mi][ni][2] * scale + b0, acc[mi][ni][3] * scale + b1};
            *(float2*)(C + (size_t)m0 * ldc + n0) = v0;
            *(float2*)(C + (size_t)(m0 + 8) * ldc + n0) = v1;
        }
    }

    if constexpr (STATS) {
        // Partial softmax stats over this 128-col tile (values = acc*scale).
        __shared__ float smr[128][4];
        __shared__ float sml[128][4];
        __shared__ float srm[128];
        // Phase A: row max
#pragma unroll
        for (int mi = 0; mi < MT; mi++) {
#pragma unroll
            for (int half = 0; half < 2; half++) {
                float lm = -INFINITY;
#pragma unroll
                for (int ni = 0; ni < NT; ni++) {
                    lm = fmaxf(lm, acc[mi][ni][2 * half] * scale);
                    lm = fmaxf(lm, acc[mi][ni][2 * half + 1] * scale);
                }
                lm = fmaxf(lm, __shfl_xor_sync(0xFFFFFFFFu, lm, 1));
                lm = fmaxf(lm, __shfl_xor_sync(0xFFFFFFFFu, lm, 2));
                if (tig == 0)
                    smr[wm * WTM + mi * 16 + g + half * 8][wn] = lm;
            }
        }
        __syncthreads();
        if (tid < 128)
            srm[tid] = fmaxf(fmaxf(smr[tid][0], smr[tid][1]),
                             fmaxf(smr[tid][2], smr[tid][3]));
        __syncthreads();
        // Phase B: row sumexp
#pragma unroll
        for (int mi = 0; mi < MT; mi++) {
#pragma unroll
            for (int half = 0; half < 2; half++) {
                int rl = wm * WTM + mi * 16 + g + half * 8;
                float rm = srm[rl];
                float ls = 0.0f;
#pragma unroll
                for (int ni = 0; ni < NT; ni++) {
                    ls += expf(acc[mi][ni][2 * half] * scale - rm);
                    ls += expf(acc[mi][ni][2 * half + 1] * scale - rm);
                }
                ls += __shfl_xor_sync(0xFFFFFFFFu, ls, 1);
                ls += __shfl_xor_sync(0xFFFFFFFFu, ls, 2);
                if (tig == 0) sml[rl][wn] = ls;
            }
        }
        __syncthreads();
        if (tid < 128) {
            float l = sml[tid][0] + sml[tid][1] + sml[tid][2] + sml[tid][3];
            size_t off = (size_t)blockIdx.x * T_LEN + blockM + tid;
            pm[off] = srm[tid];
            pl[off] = l;
        }
    }
}

// ---------------------------------------------------------------------------
// PV kernel: fused softmax-apply + P writeback + PV GEMM.
// A = raw scores (P region), Pw = same buffer (normalized writeback),
// B = Vt[bh] (64 rows x 2048), C = g_attn slice. BM=128, BN=64.
// ---------------------------------------------------------------------------
__device__ __forceinline__ void gemm_pv(
    const float* __restrict__ A, float* __restrict__ Pw, int lda,
    const float* __restrict__ B, int ldb,
    float* __restrict__ C, int ldc, int K,
    const float* __restrict__ mrow, const float* __restrict__ lrow)
{
    constexpr int BM = 128, BN = 64, BK = 32, LDW = 20;
    constexpr int WARPS_M = 4, WARPS_N = 2;
    constexpr int WTM = BM / WARPS_M;   // 32
    constexpr int WTN = BN / WARPS_N;   // 32
    constexpr int MT = WTM / 16;        // 2
    constexpr int NT = WTN / 8;         // 4

    __shared__ uint32_t As[2][BM * LDW];
    __shared__ uint32_t Bs[2][BN * LDW];

    const int tid  = threadIdx.x;
    const int lane = tid & 31;
    const int warp = tid >> 5;
    const int wm = warp % WARPS_M;
    const int wn = warp / WARPS_M;
    const int g   = lane >> 2;
    const int tig = lane & 3;

    const int blockM = blockIdx.y * BM;
    const float* Ab = A + (size_t)blockM * lda;
    float* Pb = Pw + (size_t)blockM * lda;

    // Per-thread A rows (fixed across k): j=0 -> tid>>2, j=1 -> 64+(tid>>2)
    const int r0 = tid >> 2;
    const int r1 = 64 + (tid >> 2);
    const float em[2]  = {mrow[blockM + r0], mrow[blockM + r1]};
    const float el[2]  = {lrow[blockM + r0], lrow[blockM + r1]};

    float acc[MT][NT][4];
#pragma unroll
    for (int mi = 0; mi < MT; mi++)
#pragma unroll
        for (int ni = 0; ni < NT; ni++)
#pragma unroll
            for (int j = 0; j < 4; j++) acc[mi][ni][j] = 0.0f;

    float4 ra[4], rb[2];

    auto load_tiles = [&](int k0) {
#pragma unroll
        for (int j = 0; j < 2; j++) {
            int u = tid + j * 256;
            int row = u >> 2, c = u & 3;
            const float* p = Ab + (size_t)row * lda + k0 + c * 8;
            ra[2 * j]     = *(const float4*)(p);
            ra[2 * j + 1] = *(const float4*)(p + 4);
        }
        {
            int row = tid >> 2, c = tid & 3;
            const float* p = B + (size_t)row * ldb + k0 + c * 8;
            rb[0] = *(const float4*)(p);
            rb[1] = *(const float4*)(p + 4);
        }
    };
    auto store_tiles = [&](int buf, int k0) {
#pragma unroll
        for (int j = 0; j < 2; j++) {
            int u = tid + j * 256;
            int row = u >> 2, c = u & 3;
            float m = em[j], li = el[j];
            float4 f0 = ra[2 * j], f1 = ra[2 * j + 1];
            f0.x = expf(f0.x - m) * li; f0.y = expf(f0.y - m) * li;
            f0.z = expf(f0.z - m) * li; f0.w = expf(f0.w - m) * li;
            f1.x = expf(f1.x - m) * li; f1.y = expf(f1.y - m) * li;
            f1.z = expf(f1.z - m) * li; f1.w = expf(f1.w - m) * li;
            float* pw = Pb + (size_t)row * lda + k0 + c * 8;
            *(float4*)(pw)     = f0;
            *(float4*)(pw + 4) = f1;
            uint4 v = {pack_h2(f0.x, f0.y), pack_h2(f0.z, f0.w),
                       pack_h2(f1.x, f1.y), pack_h2(f1.z, f1.w)};
            *(uint4*)&As[buf][row * LDW + c * 4] = v;
        }
        {
            int row = tid >> 2, c = tid & 3;
            float4 f0 = rb[0], f1 = rb[1];
            uint4 v = {pack_h2(f0.x, f0.y), pack_h2(f0.z, f0.w),
                       pack_h2(f1.x, f1.y), pack_h2(f1.z, f1.w)};
            *(uint4*)&Bs[buf][row * LDW + c * 4] = v;
        }
    };
    auto compute = [&](int buf) {
#pragma unroll
        for (int ks2 = 0; ks2 < 2; ks2++) {
            const int base = ks2 * 8;
            uint32_t af[MT][4];
            uint32_t bf[NT][2];
#pragma unroll
            for (int mi = 0; mi < MT; mi++) {
                int m = wm * WTM + mi * 16;
                const uint32_t* a = As[buf];
                af[mi][0] = a[(m + g) * LDW + base + tig];
                af[mi][1] = a[(m + g + 8) * LDW + base + tig];
                af[mi][2] = a[(m + g) * LDW + base + tig + 4];
                af[mi][3] = a[(m + g + 8) * LDW + base + tig + 4];
            }
#pragma unroll
            for (int ni = 0; ni < NT; ni++) {
                int n = wn * WTN + ni * 8;
                const uint32_t* b = Bs[buf];
                bf[ni][0] = b[(n + g) * LDW + base + tig];
                bf[ni][1] = b[(n + g) * LDW + base + tig + 4];
            }
#pragma unroll
            for (int mi = 0; mi < MT; mi++)
#pragma unroll
                for (int ni = 0; ni < NT; ni++)
                    mma_f16(acc[mi][ni], af[mi], bf[ni]);
        }
    };

    const int nk = K / BK;
    load_tiles(0);
    store_tiles(0, 0);
    __syncthreads();

    for (int it = 0; it < nk; it++) {
        int cur = it & 1;
        if (it + 1 < nk) load_tiles((it + 1) * BK);
        compute(cur);
        if (it + 1 < nk) {
            store_tiles(cur ^ 1, (it + 1) * BK);
            __syncthreads();
        }
    }

#pragma unroll
    for (int mi = 0; mi < MT; mi++) {
#pragma unroll
        for (int ni = 0; ni < NT; ni++) {
            int m0 = blockM + wm * WTM + mi * 16 + g;
            int n0 = wn * WTN + ni * 8 + 2 * tig;
            float2 v0 = {acc[mi][ni][0], acc[mi][ni][1]};
            float2 v1 = {acc[mi][ni][2], acc[mi][ni][3]};
            *(float2*)(C + (size_t)m0 * ldc + n0) = v0;
            *(float2*)(C + (size_t)(m0 + 8) * ldc + n0) = v1;
        }
    }
}

// ---------------------------------------------------------------------------
// Kernel wrappers
// ---------------------------------------------------------------------------
__global__ void __launch_bounds__(256) k_qkv(const float* __restrict__ g,
                                             const float* __restrict__ Win,
                                             const float* __restrict__ bin)
{
    gemm_fp16<128, 2, 4, false>(g, E_DIM, Win, E_DIM, g_qkv, E3, E_DIM, 1.0f, bin,
                                nullptr, nullptr);
}

__global__ void k_build_vt()
{
    size_t idx = (size_t)blockIdx.x * blockDim.x + threadIdx.x;
    int s = (int)(idx % T_LEN);
    int rest = (int)(idx / T_LEN);
    int d = rest % HD;
    int bh = rest / HD;
    int b = bh >> 4;
    int h = bh & 15;
    g_vt[idx] = g_qkv[(size_t)(s * B_DIM + b) * E3 + 2 * E_DIM + h * HD + d];
}

__global__ void __launch_bounds__(256) k_scores(float* __restrict__ P)
{
    int bh = blockIdx.z;
    int b = bh >> 4;
    int h = bh & 15;
    const float* A  = g_qkv + (size_t)b * E3 + h * HD;
    const float* Bm = g_qkv + (size_t)b * E3 + E_DIM + h * HD;
    float* C = P + (size_t)bh * T_LEN * T_LEN;
    float* pm = g_pm + (size_t)bh * NTILE * T_LEN;
    float* pl = g_pl + (size_t)bh * NTILE * T_LEN;
    gemm_fp16<128, 2, 4, true>(A, B_DIM * E3, Bm, B_DIM * E3, C, T_LEN, HD, 0.125f,
                               nullptr, pm, pl);
}

__global__ void k_reduce()
{
    int idx = blockIdx.x * 256 + threadIdx.x;      // 65536 rows
    int bh = idx >> 11;
    int t  = idx & 2047;
    size_t base = (size_t)bh * NTILE * T_LEN + t;
    float m = -INFINITY;
#pragma unroll
    for (int c = 0; c < NTILE; c++)
        m = fmaxf(m, g_pm[base + (size_t)c * T_LEN]);
    float l = 0.0f;
#pragma unroll
    for (int c = 0; c < NTILE; c++)
        l += g_pl[base + (size_t)c * T_LEN] * expf(g_pm[base + (size_t)c * T_LEN] - m);
    g_m[idx] = m;
    g_linv[idx] = 1.0f / l;
}

__global__ void __launch_bounds__(256) k_pv(float* __restrict__ P)
{
    int bh = blockIdx.z;
    int b = bh >> 4;
    int h = bh & 15;
    float* A  = P + (size_t)bh * T_LEN * T_LEN;
    const float* Bm = g_vt + (size_t)bh * HD * T_LEN;
    float* C = g_attn + (size_t)b * E_DIM + h * HD;
    gemm_pv(A, A, T_LEN, Bm, T_LEN, C, B_DIM * E_DIM, T_LEN,
            g_m + (size_t)bh * T_LEN, g_linv + (size_t)bh * T_LEN);
}

__global__ void __launch_bounds__(256) k_out(const float* __restrict__ Wout,
                                             const float* __restrict__ bout,
                                             float* __restrict__ out)
{
    gemm_fp16<128, 2, 4, false>(g_attn, E_DIM, Wout, E_DIM, out, E_DIM, E_DIM, 1.0f, bout,
                                nullptr, nullptr);
}

// ---------------------------------------------------------------------------
extern "C" void kernel_launch(void* const* d_in, const int* in_sizes, int n_in,
                              void* d_out, int out_size)
{
    const float* g    = (const float*)d_in[0];
    const float* Win  = (const float*)d_in[1];
    const float* bin  = (const float*)d_in[2];
    const float* Wout = (const float*)d_in[3];
    const float* bout = (const float*)d_in[4];

    float* out = (float*)d_out;
    float* P   = (float*)d_out + OUT_ELEMS;

    // 1. QKV projection
    k_qkv<<<dim3(E3 / 128, M_ROWS / 128), 256>>>(g, Win, bin);

    // 2. V transpose
    k_build_vt<<<(int)((size_t)NHEADS * HD * T_LEN / 256), 256>>>();

    // 3. Scores (raw, scaled) into P region + partial softmax stats
    k_scores<<<dim3(T_LEN / 128, T_LEN / 128, NHEADS), 256>>>(P);

    // 4. Reduce partials -> per-row (max, 1/sumexp)
    k_reduce<<<NHEADS * T_LEN / 256, 256>>>();

    // 5. Fused: normalize P in place + attn = P @ V
    k_pv<<<dim3(1, T_LEN / 128, NHEADS), 256>>>(P);

    // 6. Output projection
    k_out<<<dim3(E_DIM / 128, M_ROWS / 128), 256>>>(Wout, bout, out);
}

// round 7
// speedup vs baseline: 2.0183x; 1.1537x over previous
#include <cuda_runtime.h>
#include <cuda_fp16.h>
#include <math.h>
#include <stdint.h>

// Problem constants
#define T_LEN 2048
#define B_DIM 2
#define E_DIM 1024
#define H_NUM 16
#define HD 64
#define M_ROWS (T_LEN * B_DIM)       // 4096
#define E3 (3 * E_DIM)               // 3072
#define NHEADS (B_DIM * H_NUM)       // 32
#define NTILE (T_LEN / 128)          // 16 col tiles per row
#define OUT_ELEMS ((size_t)T_LEN * B_DIM * E_DIM)

// Scratch in device globals (all fp32)
__device__ float g_qkv[(size_t)M_ROWS * E3];        // 48 MB
__device__ float g_vt[(size_t)NHEADS * HD * T_LEN]; // 16 MB
__device__ float g_attn[(size_t)M_ROWS * E_DIM];    // 16 MB
__device__ float g_pm[(size_t)NHEADS * NTILE * T_LEN];  // partial row max
__device__ float g_pl[(size_t)NHEADS * NTILE * T_LEN];  // partial row sumexp
__device__ float g_m[(size_t)NHEADS * T_LEN];           // final row max
__device__ float g_linv[(size_t)NHEADS * T_LEN];        // final 1/sumexp

__device__ __forceinline__ uint32_t pack_h2(float lo, float hi) {
    uint32_t r;
    asm("cvt.rn.f16x2.f32 %0, %1, %2;" : "=r"(r) : "f"(hi), "f"(lo));
    return r;
}

__device__ __forceinline__ void mma_f16(float c[4], const uint32_t a[4], const uint32_t b[2]) {
    asm volatile(
        "mma.sync.aligned.m16n8k16.row.col.f32.f16.f16.f32 "
        "{%0,%1,%2,%3}, {%4,%5,%6,%7}, {%8,%9}, {%0,%1,%2,%3};\n"
        : "+f"(c[0]), "+f"(c[1]), "+f"(c[2]), "+f"(c[3])
        : "r"(a[0]), "r"(a[1]), "r"(a[2]), "r"(a[3]), "r"(b[0]), "r"(b[1]));
}

__device__ __forceinline__ void ldm_x4(uint32_t r[4], const uint32_t* p) {
    uint32_t a = (uint32_t)__cvta_generic_to_shared(p);
    asm volatile("ldmatrix.sync.aligned.m8n8.x4.shared.b16 {%0,%1,%2,%3}, [%4];"
                 : "=r"(r[0]), "=r"(r[1]), "=r"(r[2]), "=r"(r[3]) : "r"(a));
}

// ---------------------------------------------------------------------------
// fp16 tensor-core NT GEMM: C[M,N] = scale * A[M,K] @ B[N,K]^T + bias[N]
// ldmatrix fragment loads; optional STATS epilogue for softmax partials.
// NT must be even.
// ---------------------------------------------------------------------------
template <int BN, int WARPS_M, int WARPS_N, bool STATS>
__device__ __forceinline__ void gemm_fp16(
    const float* __restrict__ A, int lda,
    const float* __restrict__ B, int ldb,
    float* __restrict__ C, int ldc,
    int K, float scale, const float* __restrict__ bias,
    float* __restrict__ pm, float* __restrict__ pl)
{
    constexpr int BM = 128;
    constexpr int BK = 32;
    constexpr int LDW = 20;
    constexpr int WTM = BM / WARPS_M;
    constexpr int WTN = BN / WARPS_N;
    constexpr int MT = WTM / 16;
    constexpr int NT = WTN / 8;
    constexpr int AU = BM * 4 / 256;
    constexpr int BU = BN * 4 / 256;

    __shared__ uint32_t As[2][BM * LDW];
    __shared__ uint32_t Bs[2][BN * LDW];

    const int tid  = threadIdx.x;
    const int lane = tid & 31;
    const int warp = tid >> 5;
    const int wm = warp % WARPS_M;
    const int wn = warp / WARPS_M;
    const int g   = lane >> 2;
    const int tig = lane & 3;

    // ldmatrix lane-derived address components
    const int a_row = (lane & 7) + ((lane >> 3) & 1) * 8;   // + m
    const int a_off = (lane >> 4) * 4;                       // + base
    const int b_row = (lane & 7) + (lane >> 4) * 8;          // + n
    const int b_off = ((lane >> 3) & 1) * 4;                 // + base

    const int blockM = blockIdx.y * BM;
    const int blockN = blockIdx.x * BN;
    const float* Ab = A + (size_t)blockM * lda;
    const float* Bb = B + (size_t)blockN * ldb;

    float acc[MT][NT][4];
#pragma unroll
    for (int mi = 0; mi < MT; mi++)
#pragma unroll
        for (int ni = 0; ni < NT; ni++)
#pragma unroll
            for (int j = 0; j < 4; j++) acc[mi][ni][j] = 0.0f;

    float4 ra[2 * AU], rb[2 * BU];

    auto load_tiles = [&](int k0) {
#pragma unroll
        for (int j = 0; j < AU; j++) {
            int u = tid + j * 256;
            int row = u >> 2, c = u & 3;
            const float* p = Ab + (size_t)row * lda + k0 + c * 8;
            ra[2 * j]     = *(const float4*)(p);
            ra[2 * j + 1] = *(const float4*)(p + 4);
        }
#pragma unroll
        for (int j = 0; j < BU; j++) {
            int u = tid + j * 256;
            int row = u >> 2, c = u & 3;
            const float* p = Bb + (size_t)row * ldb + k0 + c * 8;
            rb[2 * j]     = *(const float4*)(p);
            rb[2 * j + 1] = *(const float4*)(p + 4);
        }
    };
    auto store_tiles = [&](int buf) {
#pragma unroll
        for (int j = 0; j < AU; j++) {
            int u = tid + j * 256;
            int row = u >> 2, c = u & 3;
            float4 f0 = ra[2 * j], f1 = ra[2 * j + 1];
            uint4 v = {pack_h2(f0.x, f0.y), pack_h2(f0.z, f0.w),
                       pack_h2(f1.x, f1.y), pack_h2(f1.z, f1.w)};
            *(uint4*)&As[buf][row * LDW + c * 4] = v;
        }
#pragma unroll
        for (int j = 0; j < BU; j++) {
            int u = tid + j * 256;
            int row = u >> 2, c = u & 3;
            float4 f0 = rb[2 * j], f1 = rb[2 * j + 1];
            uint4 v = {pack_h2(f0.x, f0.y), pack_h2(f0.z, f0.w),
                       pack_h2(f1.x, f1.y), pack_h2(f1.z, f1.w)};
            *(uint4*)&Bs[buf][row * LDW + c * 4] = v;
        }
    };
    auto compute = [&](int buf) {
#pragma unroll
        for (int ks2 = 0; ks2 < 2; ks2++) {
            const int base = ks2 * 8;
            uint32_t af[MT][4];
            uint32_t bf[NT][2];
#pragma unroll
            for (int mi = 0; mi < MT; mi++) {
                int m = wm * WTM + mi * 16;
                ldm_x4(af[mi], &As[buf][(m + a_row) * LDW + base + a_off]);
            }
#pragma unroll
            for (int ni = 0; ni < NT; ni += 2) {
                int n = wn * WTN + ni * 8;
                uint32_t r[4];
                ldm_x4(r, &Bs[buf][(n + b_row) * LDW + base + b_off]);
                bf[ni][0] = r[0]; bf[ni][1] = r[1];
                bf[ni + 1][0] = r[2]; bf[ni + 1][1] = r[3];
            }
#pragma unroll
            for (int mi = 0; mi < MT; mi++)
#pragma unroll
                for (int ni = 0; ni < NT; ni++)
                    mma_f16(acc[mi][ni], af[mi], bf[ni]);
        }
    };

    const int nk = K / BK;
    load_tiles(0);
    store_tiles(0);
    __syncthreads();

    for (int it = 0; it < nk; it++) {
        int cur = it & 1;
        if (it + 1 < nk) load_tiles((it + 1) * BK);
        compute(cur);
        if (it + 1 < nk) {
            store_tiles(cur ^ 1);
            __syncthreads();
        }
    }

    // Write C
#pragma unroll
    for (int mi = 0; mi < MT; mi++) {
#pragma unroll
        for (int ni = 0; ni < NT; ni++) {
            int m0 = blockM + wm * WTM + mi * 16 + g;
            int n0 = blockN + wn * WTN + ni * 8 + 2 * tig;
            float b0 = bias ? bias[n0] : 0.0f;
            float b1 = bias ? bias[n0 + 1] : 0.0f;
            float2 v0 = {acc[mi][ni][0] * scale + b0, acc[mi][ni][1] * scale + b1};
            float2 v1 = {acc[mi][ni][2] * scale + b0, acc[mi][ni][3] * scale + b1};
            *(float2*)(C + (size_t)m0 * ldc + n0) = v0;
            *(float2*)(C + (size_t)(m0 + 8) * ldc + n0) = v1;
        }
    }

    if constexpr (STATS) {
        __shared__ float smr[128][4];
        __shared__ float sml[128][4];
        __shared__ float srm[128];
#pragma unroll
        for (int mi = 0; mi < MT; mi++) {
#pragma unroll
            for (int half = 0; half < 2; half++) {
                float lm = -INFINITY;
#pragma unroll
                for (int ni = 0; ni < NT; ni++) {
                    lm = fmaxf(lm, acc[mi][ni][2 * half] * scale);
                    lm = fmaxf(lm, acc[mi][ni][2 * half + 1] * scale);
                }
                lm = fmaxf(lm, __shfl_xor_sync(0xFFFFFFFFu, lm, 1));
                lm = fmaxf(lm, __shfl_xor_sync(0xFFFFFFFFu, lm, 2));
                if (tig == 0)
                    smr[wm * WTM + mi * 16 + g + half * 8][wn] = lm;
            }
        }
        __syncthreads();
        if (tid < 128)
            srm[tid] = fmaxf(fmaxf(smr[tid][0], smr[tid][1]),
                             fmaxf(smr[tid][2], smr[tid][3]));
        __syncthreads();
#pragma unroll
        for (int mi = 0; mi < MT; mi++) {
#pragma unroll
            for (int half = 0; half < 2; half++) {
                int rl = wm * WTM + mi * 16 + g + half * 8;
                float rm = srm[rl];
                float ls = 0.0f;
#pragma unroll
                for (int ni = 0; ni < NT; ni++) {
                    ls += expf(acc[mi][ni][2 * half] * scale - rm);
                    ls += expf(acc[mi][ni][2 * half + 1] * scale - rm);
                }
                ls += __shfl_xor_sync(0xFFFFFFFFu, ls, 1);
                ls += __shfl_xor_sync(0xFFFFFFFFu, ls, 2);
                if (tig == 0) sml[rl][wn] = ls;
            }
        }
        __syncthreads();
        if (tid < 128) {
            float l = sml[tid][0] + sml[tid][1] + sml[tid][2] + sml[tid][3];
            size_t off = (size_t)blockIdx.x * T_LEN + blockM + tid;
            pm[off] = srm[tid];
            pl[off] = l;
        }
    }
}

// ---------------------------------------------------------------------------
// PV kernel: fused softmax-apply + P writeback + PV GEMM (ldmatrix fragments).
// ---------------------------------------------------------------------------
__device__ __forceinline__ void gemm_pv(
    const float* __restrict__ A, float* __restrict__ Pw, int lda,
    const float* __restrict__ B, int ldb,
    float* __restrict__ C, int ldc, int K,
    const float* __restrict__ mrow, const float* __restrict__ lrow)
{
    constexpr int BM = 128, BN = 64, BK = 32, LDW = 20;
    constexpr int WARPS_M = 4, WARPS_N = 2;
    constexpr int WTM = BM / WARPS_M;   // 32
    constexpr int WTN = BN / WARPS_N;   // 32
    constexpr int MT = WTM / 16;        // 2
    constexpr int NT = WTN / 8;         // 4

    __shared__ uint32_t As[2][BM * LDW];
    __shared__ uint32_t Bs[2][BN * LDW];

    const int tid  = threadIdx.x;
    const int lane = tid & 31;
    const int warp = tid >> 5;
    const int wm = warp % WARPS_M;
    const int wn = warp / WARPS_M;
    const int g   = lane >> 2;
    const int tig = lane & 3;

    const int a_row = (lane & 7) + ((lane >> 3) & 1) * 8;
    const int a_off = (lane >> 4) * 4;
    const int b_row = (lane & 7) + (lane >> 4) * 8;
    const int b_off = ((lane >> 3) & 1) * 4;

    const int blockM = blockIdx.y * BM;
    const float* Ab = A + (size_t)blockM * lda;
    float* Pb = Pw + (size_t)blockM * lda;

    const int r0 = tid >> 2;
    const float em[2]  = {mrow[blockM + r0], mrow[blockM + 64 + r0]};
    const float el[2]  = {lrow[blockM + r0], lrow[blockM + 64 + r0]};

    float acc[MT][NT][4];
#pragma unroll
    for (int mi = 0; mi < MT; mi++)
#pragma unroll
        for (int ni = 0; ni < NT; ni++)
#pragma unroll
            for (int j = 0; j < 4; j++) acc[mi][ni][j] = 0.0f;

    float4 ra[4], rb[2];

    auto load_tiles = [&](int k0) {
#pragma unroll
        for (int j = 0; j < 2; j++) {
            int u = tid + j * 256;
            int row = u >> 2, c = u & 3;
            const float* p = Ab + (size_t)row * lda + k0 + c * 8;
            ra[2 * j]     = *(const float4*)(p);
            ra[2 * j + 1] = *(const float4*)(p + 4);
        }
        {
            int row = tid >> 2, c = tid & 3;
            const float* p = B + (size_t)row * ldb + k0 + c * 8;
            rb[0] = *(const float4*)(p);
            rb[1] = *(const float4*)(p + 4);
        }
    };
    auto store_tiles = [&](int buf, int k0) {
#pragma unroll
        for (int j = 0; j < 2; j++) {
            int u = tid + j * 256;
            int row = u >> 2, c = u & 3;
            float m = em[j], li = el[j];
            float4 f0 = ra[2 * j], f1 = ra[2 * j + 1];
            f0.x = expf(f0.x - m) * li; f0.y = expf(f0.y - m) * li;
            f0.z = expf(f0.z - m) * li; f0.w = expf(f0.w - m) * li;
            f1.x = expf(f1.x - m) * li; f1.y = expf(f1.y - m) * li;
            f1.z = expf(f1.z - m) * li; f1.w = expf(f1.w - m) * li;
            float* pw = Pb + (size_t)row * lda + k0 + c * 8;
            *(float4*)(pw)     = f0;
            *(float4*)(pw + 4) = f1;
            uint4 v = {pack_h2(f0.x, f0.y), pack_h2(f0.z, f0.w),
                       pack_h2(f1.x, f1.y), pack_h2(f1.z, f1.w)};
            *(uint4*)&As[buf][row * LDW + c * 4] = v;
        }
        {
            int row = tid >> 2, c = tid & 3;
            float4 f0 = rb[0], f1 = rb[1];
            uint4 v = {pack_h2(f0.x, f0.y), pack_h2(f0.z, f0.w),
                       pack_h2(f1.x, f1.y), pack_h2(f1.z, f1.w)};
            *(uint4*)&Bs[buf][row * LDW + c * 4] = v;
        }
    };
    auto compute = [&](int buf) {
#pragma unroll
        for (int ks2 = 0; ks2 < 2; ks2++) {
            const int base = ks2 * 8;
            uint32_t af[MT][4];
            uint32_t bf[NT][2];
#pragma unroll
            for (int mi = 0; mi < MT; mi++) {
                int m = wm * WTM + mi * 16;
                ldm_x4(af[mi], &As[buf][(m + a_row) * LDW + base + a_off]);
            }
#pragma unroll
            for (int ni = 0; ni < NT; ni += 2) {
                int n = wn * WTN + ni * 8;
                uint32_t r[4];
                ldm_x4(r, &Bs[buf][(n + b_row) * LDW + base + b_off]);
                bf[ni][0] = r[0]; bf[ni][1] = r[1];
                bf[ni + 1][0] = r[2]; bf[ni + 1][1] = r[3];
            }
#pragma unroll
            for (int mi = 0; mi < MT; mi++)
#pragma unroll
                for (int ni = 0; ni < NT; ni++)
                    mma_f16(acc[mi][ni], af[mi], bf[ni]);
        }
    };

    const int nk = K / BK;
    load_tiles(0);
    store_tiles(0, 0);
    __syncthreads();

    for (int it = 0; it < nk; it++) {
        int cur = it & 1;
        if (it + 1 < nk) load_tiles((it + 1) * BK);
        compute(cur);
        if (it + 1 < nk) {
            store_tiles(cur ^ 1, (it + 1) * BK);
            __syncthreads();
        }
    }

#pragma unroll
    for (int mi = 0; mi < MT; mi++) {
#pragma unroll
        for (int ni = 0; ni < NT; ni++) {
            int m0 = blockM + wm * WTM + mi * 16 + g;
            int n0 = wn * WTN + ni * 8 + 2 * tig;
            float2 v0 = {acc[mi][ni][0], acc[mi][ni][1]};
            float2 v1 = {acc[mi][ni][2], acc[mi][ni][3]};
            *(float2*)(C + (size_t)m0 * ldc + n0) = v0;
            *(float2*)(C + (size_t)(m0 + 8) * ldc + n0) = v1;
        }
    }
}

// ---------------------------------------------------------------------------
// Kernel wrappers
// ---------------------------------------------------------------------------
__global__ void __launch_bounds__(256) k_qkv(const float* __restrict__ g,
                                             const float* __restrict__ Win,
                                             const float* __restrict__ bin)
{
    gemm_fp16<128, 2, 4, false>(g, E_DIM, Win, E_DIM, g_qkv, E3, E_DIM, 1.0f, bin,
                                nullptr, nullptr);
}

__global__ void k_build_vt()
{
    size_t idx = (size_t)blockIdx.x * blockDim.x + threadIdx.x;
    int s = (int)(idx % T_LEN);
    int rest = (int)(idx / T_LEN);
    int d = rest % HD;
    int bh = rest / HD;
    int b = bh >> 4;
    int h = bh & 15;
    g_vt[idx] = g_qkv[(size_t)(s * B_DIM + b) * E3 + 2 * E_DIM + h * HD + d];
}

__global__ void __launch_bounds__(256) k_scores(float* __restrict__ P)
{
    int bh = blockIdx.z;
    int b = bh >> 4;
    int h = bh & 15;
    const float* A  = g_qkv + (size_t)b * E3 + h * HD;
    const float* Bm = g_qkv + (size_t)b * E3 + E_DIM + h * HD;
    float* C = P + (size_t)bh * T_LEN * T_LEN;
    float* pm = g_pm + (size_t)bh * NTILE * T_LEN;
    float* pl = g_pl + (size_t)bh * NTILE * T_LEN;
    gemm_fp16<128, 2, 4, true>(A, B_DIM * E3, Bm, B_DIM * E3, C, T_LEN, HD, 0.125f,
                               nullptr, pm, pl);
}

__global__ void k_reduce()
{
    int idx = blockIdx.x * 256 + threadIdx.x;      // 65536 rows
    int bh = idx >> 11;
    int t  = idx & 2047;
    size_t base = (size_t)bh * NTILE * T_LEN + t;
    float m = -INFINITY;
#pragma unroll
    for (int c = 0; c < NTILE; c++)
        m = fmaxf(m, g_pm[base + (size_t)c * T_LEN]);
    float l = 0.0f;
#pragma unroll
    for (int c = 0; c < NTILE; c++)
        l += g_pl[base + (size_t)c * T_LEN] * expf(g_pm[base + (size_t)c * T_LEN] - m);
    g_m[idx] = m;
    g_linv[idx] = 1.0f / l;
}

__global__ void __launch_bounds__(256) k_pv(float* __restrict__ P)
{
    int bh = blockIdx.z;
    int b = bh >> 4;
    int h = bh & 15;
    float* A  = P + (size_t)bh * T_LEN * T_LEN;
    const float* Bm = g_vt + (size_t)bh * HD * T_LEN;
    float* C = g_attn + (size_t)b * E_DIM + h * HD;
    gemm_pv(A, A, T_LEN, Bm, T_LEN, C, B_DIM * E_DIM, T_LEN,
            g_m + (size_t)bh * T_LEN, g_linv + (size_t)bh * T_LEN);
}

__global__ void __launch_bounds__(256) k_out(const float* __restrict__ Wout,
                                             const float* __restrict__ bout,
                                             float* __restrict__ out)
{
    gemm_fp16<128, 2, 4, false>(g_attn, E_DIM, Wout, E_DIM, out, E_DIM, E_DIM, 1.0f, bout,
                                nullptr, nullptr);
}

// ---------------------------------------------------------------------------
extern "C" void kernel_launch(void* const* d_in, const int* in_sizes, int n_in,
                              void* d_out, int out_size)
{
    const float* g    = (const float*)d_in[0];
    const float* Win  = (const float*)d_in[1];
    const float* bin  = (const float*)d_in[2];
    const float* Wout = (const float*)d_in[3];
    const float* bout = (const float*)d_in[4];

    float* out = (float*)d_out;
    float* P   = (float*)d_out + OUT_ELEMS;

    // 1. QKV projection
    k_qkv<<<dim3(E3 / 128, M_ROWS / 128), 256>>>(g, Win, bin);

    // 2. V transpose
    k_build_vt<<<(int)((size_t)NHEADS * HD * T_LEN / 256), 256>>>();

    // 3. Scores (raw, scaled) into P region + partial softmax stats
    k_scores<<<dim3(T_LEN / 128, T_LEN / 128, NHEADS), 256>>>(P);

    // 4. Reduce partials -> per-row (max, 1/sumexp)
    k_reduce<<<NHEADS * T_LEN / 256, 256>>>();

    // 5. Fused: normalize P in place + attn = P @ V
    k_pv<<<dim3(1, T_LEN / 128, NHEADS), 256>>>(P);

    // 6. Output projection
    k_out<<<dim3(E_DIM / 128, M_ROWS / 128), 256>>>(Wout, bout, out);
}

// round 8
// speedup vs baseline: 2.1880x; 1.0841x over previous
#include <cuda_runtime.h>
#include <cuda_fp16.h>
#include <math.h>
#include <stdint.h>

// Problem constants
#define T_LEN 2048
#define B_DIM 2
#define E_DIM 1024
#define H_NUM 16
#define HD 64
#define M_ROWS (T_LEN * B_DIM)       // 4096
#define E3 (3 * E_DIM)               // 3072
#define NHEADS (B_DIM * H_NUM)       // 32
#define NTILE (T_LEN / 128)
#define OUT_ELEMS ((size_t)T_LEN * B_DIM * E_DIM)
#define STAGES 4

// Scratch in device globals
__device__ __half g_gh[(size_t)M_ROWS * E_DIM];      // 8 MB  (g in fp16)
__device__ __half g_winh[(size_t)E3 * E_DIM];        // 6 MB
__device__ __half g_wouth[(size_t)E_DIM * E_DIM];    // 2 MB
__device__ __half g_qkvh[(size_t)M_ROWS * E3];       // 24 MB (q pre-scaled)
__device__ __half g_vth[(size_t)NHEADS * HD * T_LEN];// 8 MB
__device__ __half g_attnh[(size_t)M_ROWS * E_DIM];   // 8 MB
__device__ float g_pm[(size_t)NHEADS * NTILE * T_LEN];
__device__ float g_pl[(size_t)NHEADS * NTILE * T_LEN];
__device__ float g_m[(size_t)NHEADS * T_LEN];
__device__ float g_linv[(size_t)NHEADS * T_LEN];

__device__ __forceinline__ uint32_t pack_h2(float lo, float hi) {
    uint32_t r;
    asm("cvt.rn.f16x2.f32 %0, %1, %2;" : "=r"(r) : "f"(hi), "f"(lo));
    return r;
}
__device__ __forceinline__ void mma_f16(float c[4], const uint32_t a[4], const uint32_t b[2]) {
    asm volatile(
        "mma.sync.aligned.m16n8k16.row.col.f32.f16.f16.f32 "
        "{%0,%1,%2,%3}, {%4,%5,%6,%7}, {%8,%9}, {%0,%1,%2,%3};\n"
        : "+f"(c[0]), "+f"(c[1]), "+f"(c[2]), "+f"(c[3])
        : "r"(a[0]), "r"(a[1]), "r"(a[2]), "r"(a[3]), "r"(b[0]), "r"(b[1]));
}
__device__ __forceinline__ void ldm_x4(uint32_t r[4], const uint32_t* p) {
    uint32_t a = (uint32_t)__cvta_generic_to_shared(p);
    asm volatile("ldmatrix.sync.aligned.m8n8.x4.shared.b16 {%0,%1,%2,%3}, [%4];"
                 : "=r"(r[0]), "=r"(r[1]), "=r"(r[2]), "=r"(r[3]) : "r"(a));
}
__device__ __forceinline__ void cp_async16(void* smem_dst, const void* gmem_src) {
    uint32_t dst = (uint32_t)__cvta_generic_to_shared(smem_dst);
    asm volatile("cp.async.ca.shared.global [%0], [%1], 16;\n" :: "r"(dst), "l"(gmem_src));
}
__device__ __forceinline__ void cp_commit() { asm volatile("cp.async.commit_group;\n"); }
template <int N>
__device__ __forceinline__ void cp_wait() { asm volatile("cp.async.wait_group %0;\n" :: "n"(N)); }

// ---------------------------------------------------------------------------
// fp16-operand NT GEMM, 4-stage cp.async + ldmatrix + m16n8k16.
// C = scale * A @ B^T + bias. BM=128, BN=128, 256 threads, BK=32 (halves).
// OUT_HALF: write fp16 (qkv); else fp32. STATS: softmax partials (scores).
// Smem rows: 20 words (16 payload + 4 pad) -> conflict-free LDSM & cp.async.
// ---------------------------------------------------------------------------
template <bool OUT_HALF, bool STATS>
__device__ __forceinline__ void gemm_h(
    const __half* __restrict__ A, int lda,
    const __half* __restrict__ B, int ldb,
    float* __restrict__ Cf, __half* __restrict__ Ch, int ldc,
    int K, float scale, const float* __restrict__ bias,
    float* __restrict__ pm, float* __restrict__ pl)
{
    constexpr int BM = 128, BN = 128, BK = 32, LDW = 20;
    constexpr int WARPS_M = 2;
    constexpr int WTM = 64, WTN = 32, MT = 4, NT = 4;
    constexpr int SA = BM * LDW;             // words per A stage
    constexpr int SB = BN * LDW;

    extern __shared__ uint32_t sm[];

    const int tid  = threadIdx.x;
    const int lane = tid & 31;
    const int warp = tid >> 5;
    const int wm = warp % WARPS_M;
    const int wn = warp / WARPS_M;
    const int g   = lane >> 2;
    const int tig = lane & 3;

    const int a_row = (lane & 7) + ((lane >> 3) & 1) * 8;
    const int a_off = (lane >> 4) * 4;
    const int b_row = (lane & 7) + (lane >> 4) * 8;
    const int b_off = ((lane >> 3) & 1) * 4;

    const int blockM = blockIdx.y * BM;
    const int blockN = blockIdx.x * BN;
    const __half* Ab = A + (size_t)blockM * lda;
    const __half* Bb = B + (size_t)blockN * ldb;

    float acc[MT][NT][4];
#pragma unroll
    for (int mi = 0; mi < MT; mi++)
#pragma unroll
        for (int ni = 0; ni < NT; ni++)
#pragma unroll
            for (int j = 0; j < 4; j++) acc[mi][ni][j] = 0.0f;

    auto issue_copy = [&](int s, int k0) {
        uint32_t* as = sm + s * (SA + SB);
        uint32_t* bs = as + SA;
#pragma unroll
        for (int j = 0; j < 2; j++) {
            int u = tid + j * 256;
            int row = u >> 2, c = u & 3;
            cp_async16(&as[row * LDW + c * 4], Ab + (size_t)row * lda + k0 + c * 8);
        }
#pragma unroll
        for (int j = 0; j < 2; j++) {
            int u = tid + j * 256;
            int row = u >> 2, c = u & 3;
            cp_async16(&bs[row * LDW + c * 4], Bb + (size_t)row * ldb + k0 + c * 8);
        }
    };
    auto compute = [&](int s) {
        const uint32_t* as = sm + s * (SA + SB);
        const uint32_t* bs = as + SA;
#pragma unroll
        for (int ks2 = 0; ks2 < 2; ks2++) {
            const int base = ks2 * 8;
            uint32_t af[MT][4];
            uint32_t bf[NT][2];
#pragma unroll
            for (int mi = 0; mi < MT; mi++) {
                int m = wm * WTM + mi * 16;
                ldm_x4(af[mi], &as[(m + a_row) * LDW + base + a_off]);
            }
#pragma unroll
            for (int ni = 0; ni < NT; ni += 2) {
                int n = wn * WTN + ni * 8;
                uint32_t r[4];
                ldm_x4(r, &bs[(n + b_row) * LDW + base + b_off]);
                bf[ni][0] = r[0]; bf[ni][1] = r[1];
                bf[ni + 1][0] = r[2]; bf[ni + 1][1] = r[3];
            }
#pragma unroll
            for (int mi = 0; mi < MT; mi++)
#pragma unroll
                for (int ni = 0; ni < NT; ni++)
                    mma_f16(acc[mi][ni], af[mi], bf[ni]);
        }
    };

    const int nk = K / BK;
#pragma unroll
    for (int s = 0; s < STAGES - 1; s++) {
        if (s < nk) issue_copy(s, s * BK);
        cp_commit();
    }
    for (int it = 0; it < nk; it++) {
        cp_wait<STAGES - 2>();
        __syncthreads();
        int nxt = it + STAGES - 1;
        if (nxt < nk) issue_copy(nxt % STAGES, nxt * BK);
        cp_commit();
        compute(it % STAGES);
    }

    // Epilogue
#pragma unroll
    for (int mi = 0; mi < MT; mi++) {
#pragma unroll
        for (int ni = 0; ni < NT; ni++) {
            int m0 = blockM + wm * WTM + mi * 16 + g;
            int n0 = blockN + wn * WTN + ni * 8 + 2 * tig;
            float b0 = bias ? bias[n0] : 0.0f;
            float b1 = bias ? bias[n0 + 1] : 0.0f;
            float v00 = (acc[mi][ni][0] + b0) * scale;
            float v01 = (acc[mi][ni][1] + b1) * scale;
            float v10 = (acc[mi][ni][2] + b0) * scale;
            float v11 = (acc[mi][ni][3] + b1) * scale;
            if constexpr (OUT_HALF) {
                *(uint32_t*)(Ch + (size_t)m0 * ldc + n0) = pack_h2(v00, v01);
                *(uint32_t*)(Ch + (size_t)(m0 + 8) * ldc + n0) = pack_h2(v10, v11);
            } else {
                *(float2*)(Cf + (size_t)m0 * ldc + n0) = make_float2(v00, v01);
                *(float2*)(Cf + (size_t)(m0 + 8) * ldc + n0) = make_float2(v10, v11);
            }
        }
    }

    if constexpr (STATS) {
        __shared__ float smr[128][4];
        __shared__ float sml[128][4];
        __shared__ float srm[128];
#pragma unroll
        for (int mi = 0; mi < MT; mi++) {
#pragma unroll
            for (int half = 0; half < 2; half++) {
                float lm = -INFINITY;
#pragma unroll
                for (int ni = 0; ni < NT; ni++) {
                    lm = fmaxf(lm, acc[mi][ni][2 * half] * scale);
                    lm = fmaxf(lm, acc[mi][ni][2 * half + 1] * scale);
                }
                lm = fmaxf(lm, __shfl_xor_sync(0xFFFFFFFFu, lm, 1));
                lm = fmaxf(lm, __shfl_xor_sync(0xFFFFFFFFu, lm, 2));
                if (tig == 0)
                    smr[wm * WTM + mi * 16 + g + half * 8][wn] = lm;
            }
        }
        __syncthreads();
        if (tid < 128)
            srm[tid] = fmaxf(fmaxf(smr[tid][0], smr[tid][1]),
                             fmaxf(smr[tid][2], smr[tid][3]));
        __syncthreads();
#pragma unroll
        for (int mi = 0; mi < MT; mi++) {
#pragma unroll
            for (int half = 0; half < 2; half++) {
                int rl = wm * WTM + mi * 16 + g + half * 8;
                float rm = srm[rl];
                float ls = 0.0f;
#pragma unroll
                for (int ni = 0; ni < NT; ni++) {
                    ls += expf(acc[mi][ni][2 * half] * scale - rm);
                    ls += expf(acc[mi][ni][2 * half + 1] * scale - rm);
                }
                ls += __shfl_xor_sync(0xFFFFFFFFu, ls, 1);
                ls += __shfl_xor_sync(0xFFFFFFFFu, ls, 2);
                if (tig == 0) sml[rl][wn] = ls;
            }
        }
        __syncthreads();
        if (tid < 128) {
            float l = sml[tid][0] + sml[tid][1] + sml[tid][2] + sml[tid][3];
            size_t off = (size_t)blockIdx.x * T_LEN + blockM + tid;
            pm[off] = srm[tid];
            pl[off] = l;
        }
    }
}

// ---------------------------------------------------------------------------
// PV kernel: fused softmax-apply + P writeback + PV GEMM. A fp32 (raw S), V fp16.
// ---------------------------------------------------------------------------
__device__ __forceinline__ void gemm_pv(
    const float* __restrict__ A, float* __restrict__ Pw, int lda,
    const __half* __restrict__ B, int ldb,
    __half* __restrict__ C, int ldc, int K,
    const float* __restrict__ mrow, const float* __restrict__ lrow)
{
    constexpr int BM = 128, BN = 64, BK = 32, LDW = 20;
    constexpr int WARPS_M = 4;
    constexpr int WTM = 32, WTN = 32, MT = 2, NT = 4;

    __shared__ uint32_t As[2][BM * LDW];
    __shared__ uint32_t Bs[2][BN * LDW];

    const int tid  = threadIdx.x;
    const int lane = tid & 31;
    const int warp = tid >> 5;
    const int wm = warp % WARPS_M;
    const int wn = warp / WARPS_M;
    const int g   = lane >> 2;
    const int tig = lane & 3;

    const int a_row = (lane & 7) + ((lane >> 3) & 1) * 8;
    const int a_off = (lane >> 4) * 4;
    const int b_row = (lane & 7) + (lane >> 4) * 8;
    const int b_off = ((lane >> 3) & 1) * 4;

    const int blockM = blockIdx.y * BM;
    const float* Ab = A + (size_t)blockM * lda;
    float* Pb = Pw + (size_t)blockM * lda;

    const int r0 = tid >> 2;
    const float em[2] = {mrow[blockM + r0], mrow[blockM + 64 + r0]};
    const float el[2] = {lrow[blockM + r0], lrow[blockM + 64 + r0]};

    float acc[MT][NT][4];
#pragma unroll
    for (int mi = 0; mi < MT; mi++)
#pragma unroll
        for (int ni = 0; ni < NT; ni++)
#pragma unroll
            for (int j = 0; j < 4; j++) acc[mi][ni][j] = 0.0f;

    float4 ra[4];
    uint4 rbv;

    auto load_tiles = [&](int k0) {
#pragma unroll
        for (int j = 0; j < 2; j++) {
            int u = tid + j * 256;
            int row = u >> 2, c = u & 3;
            const float* p = Ab + (size_t)row * lda + k0 + c * 8;
            ra[2 * j]     = *(const float4*)(p);
            ra[2 * j + 1] = *(const float4*)(p + 4);
        }
        {
            int row = tid >> 2, c = tid & 3;
            rbv = *(const uint4*)(B + (size_t)row * ldb + k0 + c * 8);
        }
    };
    auto store_tiles = [&](int buf, int k0) {
#pragma unroll
        for (int j = 0; j < 2; j++) {
            int u = tid + j * 256;
            int row = u >> 2, c = u & 3;
            float m = em[j], li = el[j];
            float4 f0 = ra[2 * j], f1 = ra[2 * j + 1];
            f0.x = expf(f0.x - m) * li; f0.y = expf(f0.y - m) * li;
            f0.z = expf(f0.z - m) * li; f0.w = expf(f0.w - m) * li;
            f1.x = expf(f1.x - m) * li; f1.y = expf(f1.y - m) * li;
            f1.z = expf(f1.z - m) * li; f1.w = expf(f1.w - m) * li;
            float* pw = Pb + (size_t)row * lda + k0 + c * 8;
            *(float4*)(pw)     = f0;
            *(float4*)(pw + 4) = f1;
            uint4 v = {pack_h2(f0.x, f0.y), pack_h2(f0.z, f0.w),
                       pack_h2(f1.x, f1.y), pack_h2(f1.z, f1.w)};
            *(uint4*)&As[buf][row * LDW + c * 4] = v;
        }
        {
            int row = tid >> 2, c = tid & 3;
            *(uint4*)&Bs[buf][row * LDW + c * 4] = rbv;
        }
    };
    auto compute = [&](int buf) {
#pragma unroll
        for (int ks2 = 0; ks2 < 2; ks2++) {
            const int base = ks2 * 8;
            uint32_t af[MT][4];
            uint32_t bf[NT][2];
#pragma unroll
            for (int mi = 0; mi < MT; mi++) {
                int m = wm * WTM + mi * 16;
                ldm_x4(af[mi], &As[buf][(m + a_row) * LDW + base + a_off]);
            }
#pragma unroll
            for (int ni = 0; ni < NT; ni += 2) {
                int n = wn * WTN + ni * 8;
                uint32_t r[4];
                ldm_x4(r, &Bs[buf][(n + b_row) * LDW + base + b_off]);
                bf[ni][0] = r[0]; bf[ni][1] = r[1];
                bf[ni + 1][0] = r[2]; bf[ni + 1][1] = r[3];
            }
#pragma unroll
            for (int mi = 0; mi < MT; mi++)
#pragma unroll
                for (int ni = 0; ni < NT; ni++)
                    mma_f16(acc[mi][ni], af[mi], bf[ni]);
        }
    };

    const int nk = K / BK;
    load_tiles(0);
    store_tiles(0, 0);
    __syncthreads();

    for (int it = 0; it < nk; it++) {
        int cur = it & 1;
        if (it + 1 < nk) load_tiles((it + 1) * BK);
        compute(cur);
        if (it + 1 < nk) {
            store_tiles(cur ^ 1, (it + 1) * BK);
            __syncthreads();
        }
    }

#pragma unroll
    for (int mi = 0; mi < MT; mi++) {
#pragma unroll
        for (int ni = 0; ni < NT; ni++) {
            int m0 = blockM + wm * WTM + mi * 16 + g;
            int n0 = wn * WTN + ni * 8 + 2 * tig;
            *(uint32_t*)(C + (size_t)m0 * ldc + n0) = pack_h2(acc[mi][ni][0], acc[mi][ni][1]);
            *(uint32_t*)(C + (size_t)(m0 + 8) * ldc + n0) = pack_h2(acc[mi][ni][2], acc[mi][ni][3]);
        }
    }
}

// ---------------------------------------------------------------------------
// Kernel wrappers
// ---------------------------------------------------------------------------
#define G4 ((size_t)M_ROWS * E_DIM / 4)
#define W4 ((size_t)E3 * E_DIM / 4)
#define O4 ((size_t)E_DIM * E_DIM / 4)

__global__ void k_cvt(const float* __restrict__ g,
                      const float* __restrict__ Win,
                      const float* __restrict__ Wout)
{
    size_t i = (size_t)blockIdx.x * blockDim.x + threadIdx.x;
    const float* src;
    __half* dst;
    size_t j;
    if (i < G4)                { src = g;    dst = g_gh;    j = i; }
    else if (i < G4 + W4)      { src = Win;  dst = g_winh;  j = i - G4; }
    else                       { src = Wout; dst = g_wouth; j = i - G4 - W4; }
    float4 v = ((const float4*)src)[j];
    uint2 h = {pack_h2(v.x, v.y), pack_h2(v.z, v.w)};
    ((uint2*)dst)[j] = h;
}

__global__ void __launch_bounds__(256) k_qkv(const float* __restrict__ bin)
{
    float qs = (blockIdx.x * 128 < E_DIM) ? 0.125f : 1.0f;
    gemm_h<true, false>(g_gh, E_DIM, g_winh, E_DIM, nullptr, g_qkvh, E3,
                        E_DIM, qs, bin, nullptr, nullptr);
}

__global__ void k_build_vt()
{
    size_t idx = (size_t)blockIdx.x * blockDim.x + threadIdx.x;
    int s = (int)(idx % T_LEN);
    int rest = (int)(idx / T_LEN);
    int d = rest % HD;
    int bh = rest / HD;
    int b = bh >> 4;
    int h = bh & 15;
    g_vth[idx] = g_qkvh[(size_t)(s * B_DIM + b) * E3 + 2 * E_DIM + h * HD + d];
}

__global__ void __launch_bounds__(256) k_scores(float* __restrict__ P)
{
    int bh = blockIdx.z;
    int b = bh >> 4;
    int h = bh & 15;
    const __half* A  = g_qkvh + (size_t)b * E3 + h * HD;
    const __half* Bm = g_qkvh + (size_t)b * E3 + E_DIM + h * HD;
    float* C = P + (size_t)bh * T_LEN * T_LEN;
    gemm_h<false, true>(A, B_DIM * E3, Bm, B_DIM * E3,
                        C, nullptr, T_LEN, HD, 1.0f, nullptr,
                        g_pm + (size_t)bh * NTILE * T_LEN,
                        g_pl + (size_t)bh * NTILE * T_LEN);
}

__global__ void k_reduce()
{
    int idx = blockIdx.x * 256 + threadIdx.x;
    int bh = idx >> 11;
    int t  = idx & 2047;
    size_t base = (size_t)bh * NTILE * T_LEN + t;
    float m = -INFINITY;
#pragma unroll
    for (int c = 0; c < NTILE; c++)
        m = fmaxf(m, g_pm[base + (size_t)c * T_LEN]);
    float l = 0.0f;
#pragma unroll
    for (int c = 0; c < NTILE; c++)
        l += g_pl[base + (size_t)c * T_LEN] * expf(g_pm[base + (size_t)c * T_LEN] - m);
    g_m[idx] = m;
    g_linv[idx] = 1.0f / l;
}

__global__ void __launch_bounds__(256) k_pv(float* __restrict__ P)
{
    int bh = blockIdx.z;
    int b = bh >> 4;
    int h = bh & 15;
    float* A  = P + (size_t)bh * T_LEN * T_LEN;
    const __half* Bm = g_vth + (size_t)bh * HD * T_LEN;
    __half* C = g_attnh + (size_t)b * E_DIM + h * HD;
    gemm_pv(A, A, T_LEN, Bm, T_LEN, C, B_DIM * E_DIM, T_LEN,
            g_m + (size_t)bh * T_LEN, g_linv + (size_t)bh * T_LEN);
}

__global__ void __launch_bounds__(256) k_out(const float* __restrict__ bout,
                                             float* __restrict__ out)
{
    gemm_h<false, false>(g_attnh, E_DIM, g_wouth, E_DIM, out, nullptr, E_DIM,
                         E_DIM, 1.0f, bout, nullptr, nullptr);
}

// ---------------------------------------------------------------------------
extern "C" void kernel_launch(void* const* d_in, const int* in_sizes, int n_in,
                              void* d_out, int out_size)
{
    const float* g    = (const float*)d_in[0];
    const float* Win  = (const float*)d_in[1];
    const float* bin  = (const float*)d_in[2];
    const float* Wout = (const float*)d_in[3];
    const float* bout = (const float*)d_in[4];

    float* out = (float*)d_out;
    float* P   = (float*)d_out + OUT_ELEMS;

    constexpr int SMEM_G = STAGES * (128 + 128) * 20 * 4;  // 81920 bytes

    static bool attr_set = false;
    if (!attr_set) {
        cudaFuncSetAttribute(k_qkv,    cudaFuncAttributeMaxDynamicSharedMemorySize, SMEM_G);
        cudaFuncSetAttribute(k_scores, cudaFuncAttributeMaxDynamicSharedMemorySize, SMEM_G);
        cudaFuncSetAttribute(k_out,    cudaFuncAttributeMaxDynamicSharedMemorySize, SMEM_G);
        attr_set = true;
    }

    // 0. Convert inputs to fp16
    k_cvt<<<(int)((G4 + W4 + O4) / 256), 256>>>(g, Win, Wout);

    // 1. QKV projection (fp16 out, q pre-scaled)
    k_qkv<<<dim3(E3 / 128, M_ROWS / 128), 256, SMEM_G>>>(bin);

    // 2. V transpose (fp16)
    k_build_vt<<<(int)((size_t)NHEADS * HD * T_LEN / 256), 256>>>();

    // 3. Scores (raw) into P region + partial softmax stats
    k_scores<<<dim3(T_LEN / 128, T_LEN / 128, NHEADS), 256, SMEM_G>>>(P);

    // 4. Reduce partials
    k_reduce<<<NHEADS * T_LEN / 256, 256>>>();

    // 5. Fused: normalize P in place + attn = P @ V (fp16 attn out)
    k_pv<<<dim3(1, T_LEN / 128, NHEADS), 256>>>(P);

    // 6. Output projection
    k_out<<<dim3(E_DIM / 128, M_ROWS / 128), 256, SMEM_G>>>(bout, out);
}